// round 4
// baseline (speedup 1.0000x reference)
#include <cuda_runtime.h>
#include <cuda_fp16.h>
#include <cstdint>

#define B_   4
#define N_   50000
#define F_   64
#define E_   800000
#define ROWS_TOTAL (B_ * N_)          // 200000
#define E2_  (2 * E_)                 // 1600000
#define N2_  (2 * N_)                 // 100000
#define SCAN_THREADS 1024
#define SCAN_CHUNK   104              // ints per thread (26 int4)
#define N2P_ (SCAN_THREADS * SCAN_CHUNK)   // 106496 padded

#define GEMM_BLOCKS (ROWS_TOTAL / 32)      // 6250
#define HIST_BLOCKS ((E2_ + 255) / 256)    // 6250

// ---------------------------------------------------------------------------
// Static device scratch
// ---------------------------------------------------------------------------
__device__ __half2 g_preh[2ull * ROWS_TOTAL * 32];   // fp16 pre-activations (51.2MB)
__device__ int     g_count[N2P_];
__device__ int     g_offs[N2P_];
__device__ int     g_cursor[N2P_];
__device__ int2    g_csr_cv[E2_];                    // packed (col, val-bits)

// ---------------------------------------------------------------------------
// zero counters (int4 vectorized)
// ---------------------------------------------------------------------------
__global__ void zero_kernel() {
    int i = blockIdx.x * blockDim.x + threadIdx.x;
    if (i < N2P_ / 4) ((int4*)g_count)[i] = make_int4(0, 0, 0, 0);
}

// ---------------------------------------------------------------------------
// Fused: blocks [0, GEMM_BLOCKS) do pre = x@W; blocks after do histogram.
// ---------------------------------------------------------------------------
__global__ __launch_bounds__(256) void gemm_hist_kernel(const float* __restrict__ x,
                                                        const float* __restrict__ W1,
                                                        const float* __restrict__ W2,
                                                        const int* __restrict__ rows1,
                                                        const int* __restrict__ rows2) {
    __shared__ float W1s[64 * 64];
    __shared__ float W2s[64 * 64];
    __shared__ float xs[64][33];

    int tid = threadIdx.x;

    if (blockIdx.x >= GEMM_BLOCKS) {
        // ---- histogram part ----
        int t = (blockIdx.x - GEMM_BLOCKS) * 256 + tid;
        if (t < E2_) {
            int idx = (t < E_) ? __ldg(rows1 + t) : (N_ + __ldg(rows2 + (t - E_)));
            atomicAdd(&g_count[idx], 1);
        }
        return;
    }

    // ---- GEMM part ----
    for (int i = tid; i < 64 * 64; i += 256) {
        W1s[i] = W1[i];
        W2s[i] = W2[i];
    }
    int row0 = blockIdx.x * 32;
    const float4* xg = (const float4*)(x + (size_t)row0 * F_);
    for (int i = tid; i < 512; i += 256) {
        float4 v = xg[i];
        int r = i >> 4;
        int k = (i & 15) * 4;
        xs[k][r] = v.x; xs[k + 1][r] = v.y; xs[k + 2][r] = v.z; xs[k + 3][r] = v.w;
    }
    __syncthreads();

    int fpair = tid & 31;
    int rg    = tid >> 5;

    unsigned long long a1[4] = {0ull, 0ull, 0ull, 0ull};
    unsigned long long a2[4] = {0ull, 0ull, 0ull, 0ull};

#pragma unroll
    for (int k = 0; k < 64; k++) {
        unsigned long long w1p = *(const unsigned long long*)&W1s[k * 64 + fpair * 2];
        unsigned long long w2p = *(const unsigned long long*)&W2s[k * 64 + fpair * 2];
#pragma unroll
        for (int r = 0; r < 4; r++) {
            float xv = xs[k][rg * 4 + r];
            unsigned long long xp;
            asm("mov.b64 %0, {%1, %1};" : "=l"(xp) : "f"(xv));
            asm("fma.rn.f32x2 %0, %1, %2, %0;" : "+l"(a1[r]) : "l"(xp), "l"(w1p));
            asm("fma.rn.f32x2 %0, %1, %2, %0;" : "+l"(a2[r]) : "l"(xp), "l"(w2p));
        }
    }

    const size_t sup_stride = (size_t)ROWS_TOTAL * 32;
#pragma unroll
    for (int r = 0; r < 4; r++) {
        size_t row = (size_t)(row0 + rg * 4 + r);
        float lo, hi;
        asm("mov.b64 {%0, %1}, %2;" : "=f"(lo), "=f"(hi) : "l"(a1[r]));
        g_preh[row * 32 + fpair] = __floats2half2_rn(lo, hi);
        asm("mov.b64 {%0, %1}, %2;" : "=f"(lo), "=f"(hi) : "l"(a2[r]));
        g_preh[sup_stride + row * 32 + fpair] = __floats2half2_rn(lo, hi);
    }
}

// ---------------------------------------------------------------------------
// Single-block exclusive scan of g_count -> g_offs, also g_cursor = g_offs.
// 1024 threads, 104 ints each (26 int4), two passes over L2-resident data.
// ---------------------------------------------------------------------------
__global__ __launch_bounds__(SCAN_THREADS) void scan_kernel() {
    __shared__ int sm[SCAN_THREADS];
    int t = threadIdx.x;
    const int4* cnt4 = (const int4*)g_count;

    // pass 1: per-thread sum
    int s = 0;
#pragma unroll
    for (int j = 0; j < SCAN_CHUNK / 4; j++) {
        int4 v = cnt4[t * (SCAN_CHUNK / 4) + j];
        s += v.x + v.y + v.z + v.w;
    }
    sm[t] = s;
    __syncthreads();

    // inclusive Hillis-Steele over 1024
#pragma unroll
    for (int off = 1; off < SCAN_THREADS; off <<= 1) {
        int add = (t >= off) ? sm[t - off] : 0;
        __syncthreads();
        sm[t] += add;
        __syncthreads();
    }
    int run = sm[t] - s;   // exclusive prefix for this thread

    // pass 2: write offsets + cursors
    int4* offs4 = (int4*)g_offs;
    int4* curs4 = (int4*)g_cursor;
#pragma unroll
    for (int j = 0; j < SCAN_CHUNK / 4; j++) {
        int4 v = cnt4[t * (SCAN_CHUNK / 4) + j];
        int4 o;
        o.x = run;
        o.y = o.x + v.x;
        o.z = o.y + v.y;
        o.w = o.z + v.z;
        run  = o.w + v.w;
        offs4[t * (SCAN_CHUNK / 4) + j] = o;
        curs4[t * (SCAN_CHUNK / 4) + j] = o;
    }
}

// ---------------------------------------------------------------------------
// scatter edges into CSR slots (packed col+val)
// ---------------------------------------------------------------------------
__global__ __launch_bounds__(256) void fill_kernel(const int* __restrict__ rows1,
                                                   const int* __restrict__ cols1,
                                                   const float* __restrict__ vals1,
                                                   const int* __restrict__ rows2,
                                                   const int* __restrict__ cols2,
                                                   const float* __restrict__ vals2) {
    int t = blockIdx.x * blockDim.x + threadIdx.x;
    if (t >= E2_) return;
    int c; float v; int idx;
    if (t < E_) {
        idx = __ldg(rows1 + t);
        c   = __ldg(cols1 + t);
        v   = __ldg(vals1 + t);
    } else {
        int e = t - E_;
        idx = N_ + __ldg(rows2 + e);
        c   = __ldg(cols2 + e);
        v   = __ldg(vals2 + e);
    }
    int slot = atomicAdd(&g_cursor[idx], 1);
    g_csr_cv[slot] = make_int2(c, __float_as_int(v));
}

// ---------------------------------------------------------------------------
// Gather SpMM + bias + relu, fused. 2 warps per row; each warp owns 2 batches.
// ---------------------------------------------------------------------------
__global__ __launch_bounds__(256) void gather_kernel(const float* __restrict__ bias,
                                                     float* __restrict__ out) {
    int gw   = (blockIdx.x * blockDim.x + threadIdx.x) >> 5;
    int lane = threadIdx.x & 31;
    if (gw >= 2 * N_) return;
    int row = gw >> 1;
    int b0  = (gw & 1) * 2;          // batches b0, b0+1

    float bx = __ldg(bias + lane * 2);
    float by = __ldg(bias + lane * 2 + 1);
    float2 acc0 = make_float2(bx, by);
    float2 acc1 = make_float2(bx, by);

    const size_t sup_stride = (size_t)ROWS_TOTAL * 32;
    const size_t bstride    = (size_t)N_ * 32;

#pragma unroll
    for (int s = 0; s < 2; s++) {
        int idx   = s * N_ + row;
        int start = g_offs[idx];
        int deg   = g_count[idx];
        const __half2* pre = g_preh + (size_t)s * sup_stride + (size_t)b0 * bstride + lane;

        for (int c0 = 0; c0 < deg; c0 += 32) {
            int nc = min(32, deg - c0);
            int2 cv = make_int2(0, 0);
            if (lane < nc) cv = __ldg(g_csr_cv + start + c0 + lane);
            for (int i = 0; i < nc; i++) {
                int   ci = __shfl_sync(0xffffffffu, cv.x, i);
                float vi = __int_as_float(__shfl_sync(0xffffffffu, cv.y, i));
                const __half2* src = pre + (size_t)ci * 32;
                __half2 h0 = __ldg(src);
                __half2 h1 = __ldg(src + bstride);
                float2 f0 = __half22float2(h0);
                float2 f1 = __half22float2(h1);
                acc0.x = fmaf(vi, f0.x, acc0.x);
                acc0.y = fmaf(vi, f0.y, acc0.y);
                acc1.x = fmaf(vi, f1.x, acc1.x);
                acc1.y = fmaf(vi, f1.y, acc1.y);
            }
        }
    }

    float2* outv = (float2*)out;
    float2 o0, o1;
    o0.x = fmaxf(acc0.x, 0.f); o0.y = fmaxf(acc0.y, 0.f);
    o1.x = fmaxf(acc1.x, 0.f); o1.y = fmaxf(acc1.y, 0.f);
    outv[((size_t)b0 * N_ + row) * 32 + lane]       = o0;
    outv[((size_t)(b0 + 1) * N_ + row) * 32 + lane] = o1;
}

extern "C" void kernel_launch(void* const* d_in, const int* in_sizes, int n_in,
                              void* d_out, int out_size) {
    const float* x     = (const float*)d_in[0];
    const int*   rows1 = (const int*)  d_in[1];
    const int*   cols1 = (const int*)  d_in[2];
    const float* vals1 = (const float*)d_in[3];
    const int*   rows2 = (const int*)  d_in[4];
    const int*   cols2 = (const int*)  d_in[5];
    const float* vals2 = (const float*)d_in[6];
    const float* W1    = (const float*)d_in[7];
    const float* W2    = (const float*)d_in[8];
    const float* bias  = (const float*)d_in[9];
    float*       out   = (float*)d_out;

    // 1) zero counters
    zero_kernel<<<(N2P_ / 4 + 255) / 256, 256>>>();

    // 2) fused GEMM (fp16 pre) + row histogram
    gemm_hist_kernel<<<GEMM_BLOCKS + HIST_BLOCKS, 256>>>(x, W1, W2, rows1, rows2);

    // 3) single-block scan -> offs + cursors
    scan_kernel<<<1, SCAN_THREADS>>>();

    // 4) CSR fill (packed col/val)
    fill_kernel<<<(E2_ + 255) / 256, 256>>>(rows1, cols1, vals1, rows2, cols2, vals2);

    // 5) fused gather + bias + relu (2 warps per row)
    gather_kernel<<<(2 * N_ * 32 + 255) / 256, 256>>>(bias, out);
}

// round 5
// speedup vs baseline: 1.0788x; 1.0788x over previous
#include <cuda_runtime.h>
#include <cuda_fp16.h>
#include <cstdint>

#define B_   4
#define N_   50000
#define F_   64
#define E_   800000
#define ROWS_TOTAL (B_ * N_)          // 200000
#define E2_  (2 * E_)                 // 1600000
#define N2_  (2 * N_)                 // 100000
#define SCAN_THREADS 1024
#define SCAN_CHUNK   104              // ints per thread (26 int4)
#define N2P_ (SCAN_THREADS * SCAN_CHUNK)   // 106496 padded

// ---------------------------------------------------------------------------
// Static device scratch
// ---------------------------------------------------------------------------
// pre-activations fp16, layout [support][node][batch][64 half]  (51.2 MB)
// -> one node = 512B contiguous block (4 batches x 128B)
__device__ __half2 g_preh[2ull * N_ * B_ * 32];
__device__ int     g_count[N2P_];
__device__ int     g_offs[N2P_];
__device__ int     g_cursor[N2P_];
__device__ int2    g_csr_cv[E2_];     // packed (col, val-bits)

// ---------------------------------------------------------------------------
// zero counters
// ---------------------------------------------------------------------------
__global__ void zero_kernel() {
    int i = blockIdx.x * blockDim.x + threadIdx.x;
    if (i < N2P_ / 4) ((int4*)g_count)[i] = make_int4(0, 0, 0, 0);
}

// ---------------------------------------------------------------------------
// histogram of destination rows, both supports
// ---------------------------------------------------------------------------
__global__ __launch_bounds__(256) void hist_kernel(const int* __restrict__ rows1,
                                                   const int* __restrict__ rows2) {
    int t = blockIdx.x * blockDim.x + threadIdx.x;
    if (t >= E2_) return;
    int idx = (t < E_) ? __ldg(rows1 + t) : (N_ + __ldg(rows2 + (t - E_)));
    atomicAdd(&g_count[idx], 1);
}

// ---------------------------------------------------------------------------
// Single-block exclusive scan of g_count -> g_offs and g_cursor.
// ---------------------------------------------------------------------------
__global__ __launch_bounds__(SCAN_THREADS) void scan_kernel() {
    __shared__ int sm[SCAN_THREADS];
    int t = threadIdx.x;
    const int4* cnt4 = (const int4*)g_count;

    int s = 0;
#pragma unroll
    for (int j = 0; j < SCAN_CHUNK / 4; j++) {
        int4 v = cnt4[t * (SCAN_CHUNK / 4) + j];
        s += v.x + v.y + v.z + v.w;
    }
    sm[t] = s;
    __syncthreads();
#pragma unroll
    for (int off = 1; off < SCAN_THREADS; off <<= 1) {
        int add = (t >= off) ? sm[t - off] : 0;
        __syncthreads();
        sm[t] += add;
        __syncthreads();
    }
    int run = sm[t] - s;

    int4* offs4 = (int4*)g_offs;
    int4* curs4 = (int4*)g_cursor;
#pragma unroll
    for (int j = 0; j < SCAN_CHUNK / 4; j++) {
        int4 v = cnt4[t * (SCAN_CHUNK / 4) + j];
        int4 o;
        o.x = run;
        o.y = o.x + v.x;
        o.z = o.y + v.y;
        o.w = o.z + v.z;
        run  = o.w + v.w;
        offs4[t * (SCAN_CHUNK / 4) + j] = o;
        curs4[t * (SCAN_CHUNK / 4) + j] = o;
    }
}

// ---------------------------------------------------------------------------
// scatter edges into CSR slots (packed col+val)
// ---------------------------------------------------------------------------
__global__ __launch_bounds__(256) void fill_kernel(const int* __restrict__ rows1,
                                                   const int* __restrict__ cols1,
                                                   const float* __restrict__ vals1,
                                                   const int* __restrict__ rows2,
                                                   const int* __restrict__ cols2,
                                                   const float* __restrict__ vals2) {
    int t = blockIdx.x * blockDim.x + threadIdx.x;
    if (t >= E2_) return;
    int c; float v; int idx;
    if (t < E_) {
        idx = __ldg(rows1 + t);
        c   = __ldg(cols1 + t);
        v   = __ldg(vals1 + t);
    } else {
        int e = t - E_;
        idx = N_ + __ldg(rows2 + e);
        c   = __ldg(cols2 + e);
        v   = __ldg(vals2 + e);
    }
    int slot = atomicAdd(&g_cursor[idx], 1);
    g_csr_cv[slot] = make_int2(c, __float_as_int(v));
}

// ---------------------------------------------------------------------------
// pre = x@W (both supports) with packed fma.rn.f32x2; fp16 output in
// [support][node][batch][64 half] layout.
// 32 flattened rows/block, 256 threads: thread = (fpair = tid&31, rg = tid>>5).
// ---------------------------------------------------------------------------
__global__ __launch_bounds__(256) void gemm_kernel(const float* __restrict__ x,
                                                   const float* __restrict__ W1,
                                                   const float* __restrict__ W2) {
    __shared__ float W1s[64 * 64];
    __shared__ float W2s[64 * 64];
    __shared__ float xs[64][33];

    int tid = threadIdx.x;
    for (int i = tid; i < 64 * 64; i += 256) {
        W1s[i] = W1[i];
        W2s[i] = W2[i];
    }
    int row0 = blockIdx.x * 32;
    const float4* xg = (const float4*)(x + (size_t)row0 * F_);
    for (int i = tid; i < 512; i += 256) {
        float4 v = xg[i];
        int r = i >> 4;
        int k = (i & 15) * 4;
        xs[k][r] = v.x; xs[k + 1][r] = v.y; xs[k + 2][r] = v.z; xs[k + 3][r] = v.w;
    }
    __syncthreads();

    int fpair = tid & 31;
    int rg    = tid >> 5;

    unsigned long long a1[4] = {0ull, 0ull, 0ull, 0ull};
    unsigned long long a2[4] = {0ull, 0ull, 0ull, 0ull};

#pragma unroll
    for (int k = 0; k < 64; k++) {
        unsigned long long w1p = *(const unsigned long long*)&W1s[k * 64 + fpair * 2];
        unsigned long long w2p = *(const unsigned long long*)&W2s[k * 64 + fpair * 2];
#pragma unroll
        for (int r = 0; r < 4; r++) {
            float xv = xs[k][rg * 4 + r];
            unsigned long long xp;
            asm("mov.b64 %0, {%1, %1};" : "=l"(xp) : "f"(xv));
            asm("fma.rn.f32x2 %0, %1, %2, %0;" : "+l"(a1[r]) : "l"(xp), "l"(w1p));
            asm("fma.rn.f32x2 %0, %1, %2, %0;" : "+l"(a2[r]) : "l"(xp), "l"(w2p));
        }
    }

    const size_t sup_stride = (size_t)N_ * B_ * 32;   // half2 units
#pragma unroll
    for (int r = 0; r < 4; r++) {
        int row = row0 + rg * 4 + r;       // flattened b*N + n
        int b = row / N_;
        int n = row - b * N_;
        size_t base = ((size_t)n * B_ + b) * 32;
        float lo, hi;
        asm("mov.b64 {%0, %1}, %2;" : "=f"(lo), "=f"(hi) : "l"(a1[r]));
        g_preh[base + fpair] = __floats2half2_rn(lo, hi);
        asm("mov.b64 {%0, %1}, %2;" : "=f"(lo), "=f"(hi) : "l"(a2[r]));
        g_preh[sup_stride + base + fpair] = __floats2half2_rn(lo, hi);
    }
}

// ---------------------------------------------------------------------------
// Gather SpMM + bias + relu, fused. One warp per output row, all 4 batches.
// Lane l = (batch = l>>3, 16B-chunk fo = l&7): one LDG.128 per edge fetches
// the whole 512B node block (4 batches x 128B). Each lane accumulates
// features fo*8..fo*8+7 of its batch in fp32.
// ---------------------------------------------------------------------------
__global__ __launch_bounds__(256) void gather_kernel(const float* __restrict__ bias,
                                                     float* __restrict__ out) {
    int row  = (blockIdx.x * blockDim.x + threadIdx.x) >> 5;
    int lane = threadIdx.x & 31;
    if (row >= N_) return;
    int b  = lane >> 3;
    int fo = lane & 7;          // 8-feature chunk

    float acc[8];
#pragma unroll
    for (int j = 0; j < 8; j++) acc[j] = __ldg(bias + fo * 8 + j);

    const size_t sup_stride_u4 = (size_t)N_ * B_ * 8;   // uint4 units (512B/node)

#pragma unroll
    for (int s = 0; s < 2; s++) {
        int idx   = s * N_ + row;
        int start = g_offs[idx];
        int deg   = g_count[idx];
        const uint4* pre = (const uint4*)g_preh + (size_t)s * sup_stride_u4 + lane;

        for (int c0 = 0; c0 < deg; c0 += 32) {
            int nc = min(32, deg - c0);
            int2 cv = make_int2(0, 0);
            if (lane < nc) cv = __ldg(g_csr_cv + start + c0 + lane);
            for (int i = 0; i < nc; i++) {
                int   ci = __shfl_sync(0xffffffffu, cv.x, i);
                float vi = __int_as_float(__shfl_sync(0xffffffffu, cv.y, i));
                uint4 h  = __ldg(pre + (size_t)ci * 32);   // 32 uint4 per node block
                float2 f0 = __half22float2(*(const __half2*)&h.x);
                float2 f1 = __half22float2(*(const __half2*)&h.y);
                float2 f2 = __half22float2(*(const __half2*)&h.z);
                float2 f3 = __half22float2(*(const __half2*)&h.w);
                acc[0] = fmaf(vi, f0.x, acc[0]);
                acc[1] = fmaf(vi, f0.y, acc[1]);
                acc[2] = fmaf(vi, f1.x, acc[2]);
                acc[3] = fmaf(vi, f1.y, acc[3]);
                acc[4] = fmaf(vi, f2.x, acc[4]);
                acc[5] = fmaf(vi, f2.y, acc[5]);
                acc[6] = fmaf(vi, f3.x, acc[6]);
                acc[7] = fmaf(vi, f3.y, acc[7]);
            }
        }
    }

    // out[b][row][fo*8 .. fo*8+7] = relu(acc)
    float4* outv = (float4*)(out + ((size_t)b * N_ + row) * F_ + fo * 8);
    float4 o0, o1;
    o0.x = fmaxf(acc[0], 0.f); o0.y = fmaxf(acc[1], 0.f);
    o0.z = fmaxf(acc[2], 0.f); o0.w = fmaxf(acc[3], 0.f);
    o1.x = fmaxf(acc[4], 0.f); o1.y = fmaxf(acc[5], 0.f);
    o1.z = fmaxf(acc[6], 0.f); o1.w = fmaxf(acc[7], 0.f);
    outv[0] = o0;
    outv[1] = o1;
}

extern "C" void kernel_launch(void* const* d_in, const int* in_sizes, int n_in,
                              void* d_out, int out_size) {
    const float* x     = (const float*)d_in[0];
    const int*   rows1 = (const int*)  d_in[1];
    const int*   cols1 = (const int*)  d_in[2];
    const float* vals1 = (const float*)d_in[3];
    const int*   rows2 = (const int*)  d_in[4];
    const int*   cols2 = (const int*)  d_in[5];
    const float* vals2 = (const float*)d_in[6];
    const float* W1    = (const float*)d_in[7];
    const float* W2    = (const float*)d_in[8];
    const float* bias  = (const float*)d_in[9];
    float*       out   = (float*)d_out;

    zero_kernel<<<(N2P_ / 4 + 255) / 256, 256>>>();
    hist_kernel<<<(E2_ + 255) / 256, 256>>>(rows1, rows2);
    scan_kernel<<<1, SCAN_THREADS>>>();
    fill_kernel<<<(E2_ + 255) / 256, 256>>>(rows1, cols1, vals1, rows2, cols2, vals2);
    gemm_kernel<<<ROWS_TOTAL / 32, 256>>>(x, W1, W2);
    gather_kernel<<<(N_ * 32 + 255) / 256, 256>>>(bias, out);
}